// round 1
// baseline (speedup 1.0000x reference)
#include <cuda_runtime.h>
#include <math.h>

// HyperConnections on GB300.
// Algebraic collapse: out[(b,so),t,d] = sum_s M[so][s] * in[(b,s),t,d]
//   M[so][s] = H_res[so][s] + H_post[so] * H_pre[s]
// H_res = Sinkhorn(H_res_logits, 10 iters, tau=0.05), H_pre/H_post = softmax.
//
// Shapes: residuals [B*S, T, D] = [8, 4096, 2048] fp32. Plane = T*D = 2^23 floats
//         = 2^21 float4. B=2, S=4.

#define NSTREAMS 4
#define PLANE_F4 (4096 * 2048 / 4)   // 2097152 = 1 << 21
#define PLANE_SHIFT 21
#define NB 2

__device__ float g_M[16];

// ---------------------------------------------------------------------------
// Setup: Sinkhorn (log-domain, 10 iters) + softmaxes -> combined 4x4 mix M.
// Single thread; total work ~300 transcendental ops.
// ---------------------------------------------------------------------------
__global__ void hc_setup_kernel(const float* __restrict__ res_logits,
                                const float* __restrict__ pre_logits,
                                const float* __restrict__ post_logits) {
    if (threadIdx.x != 0 || blockIdx.x != 0) return;

    const float tau = 0.05f;
    float Z[NSTREAMS][NSTREAMS];
    #pragma unroll
    for (int i = 0; i < NSTREAMS; i++)
        #pragma unroll
        for (int j = 0; j < NSTREAMS; j++)
            Z[i][j] = res_logits[i * NSTREAMS + j] / tau;

    float u[NSTREAMS], v[NSTREAMS];
    #pragma unroll
    for (int i = 0; i < NSTREAMS; i++) { u[i] = 0.0f; v[i] = 0.0f; }

    const float log_marginal = -logf((float)NSTREAMS);

    for (int it = 0; it < 10; it++) {
        // u = log_marginal - logsumexp_j(Z[i][j] + v[j])
        #pragma unroll
        for (int i = 0; i < NSTREAMS; i++) {
            float m = -INFINITY;
            #pragma unroll
            for (int j = 0; j < NSTREAMS; j++) m = fmaxf(m, Z[i][j] + v[j]);
            float s = 0.0f;
            #pragma unroll
            for (int j = 0; j < NSTREAMS; j++) s += expf(Z[i][j] + v[j] - m);
            u[i] = log_marginal - (m + logf(s));
        }
        // v = log_marginal - logsumexp_i(Z[i][j] + u[i])   (uses updated u)
        #pragma unroll
        for (int j = 0; j < NSTREAMS; j++) {
            float m = -INFINITY;
            #pragma unroll
            for (int i = 0; i < NSTREAMS; i++) m = fmaxf(m, Z[i][j] + u[i]);
            float s = 0.0f;
            #pragma unroll
            for (int i = 0; i < NSTREAMS; i++) s += expf(Z[i][j] + u[i] - m);
            v[j] = log_marginal - (m + logf(s));
        }
    }

    // softmax(H_pre_logits), softmax(H_post_logits)
    float Hpre[NSTREAMS], Hpost[NSTREAMS];
    {
        float m = -INFINITY;
        #pragma unroll
        for (int i = 0; i < NSTREAMS; i++) m = fmaxf(m, pre_logits[i]);
        float s = 0.0f;
        #pragma unroll
        for (int i = 0; i < NSTREAMS; i++) { Hpre[i] = expf(pre_logits[i] - m); s += Hpre[i]; }
        #pragma unroll
        for (int i = 0; i < NSTREAMS; i++) Hpre[i] /= s;
    }
    {
        float m = -INFINITY;
        #pragma unroll
        for (int i = 0; i < NSTREAMS; i++) m = fmaxf(m, post_logits[i]);
        float s = 0.0f;
        #pragma unroll
        for (int i = 0; i < NSTREAMS; i++) { Hpost[i] = expf(post_logits[i] - m); s += Hpost[i]; }
        #pragma unroll
        for (int i = 0; i < NSTREAMS; i++) Hpost[i] /= s;
    }

    // M[so][s] = H_res[so][s] + H_post[so]*H_pre[s],  H_res = exp(Z+u+v)*n
    #pragma unroll
    for (int so = 0; so < NSTREAMS; so++)
        #pragma unroll
        for (int s = 0; s < NSTREAMS; s++)
            g_M[so * NSTREAMS + s] =
                expf(Z[so][s] + u[so] + v[s]) * (float)NSTREAMS + Hpost[so] * Hpre[s];
}

// ---------------------------------------------------------------------------
// Streaming 4x4 stream mix. One float4 per thread per stream plane.
// Traffic: 256 MB read + 256 MB write, each element touched exactly once.
// ---------------------------------------------------------------------------
__global__ __launch_bounds__(256, 8)
void hc_mix_kernel(const float4* __restrict__ x, float4* __restrict__ out) {
    __shared__ float sM[16];
    if (threadIdx.x < 16) sM[threadIdx.x] = g_M[threadIdx.x];
    __syncthreads();

    unsigned idx = blockIdx.x * 256u + threadIdx.x;      // over B * PLANE_F4
    unsigned b   = idx >> PLANE_SHIFT;                    // 0..1
    unsigned i   = idx & (PLANE_F4 - 1u);

    const float4* base = x   + (size_t)b * (NSTREAMS * (size_t)PLANE_F4) + i;
    float4*       ob   = out + (size_t)b * (NSTREAMS * (size_t)PLANE_F4) + i;

    float4 v0 = __ldg(base + 0 * (size_t)PLANE_F4);
    float4 v1 = __ldg(base + 1 * (size_t)PLANE_F4);
    float4 v2 = __ldg(base + 2 * (size_t)PLANE_F4);
    float4 v3 = __ldg(base + 3 * (size_t)PLANE_F4);

    #pragma unroll
    for (int so = 0; so < NSTREAMS; so++) {
        const float a = sM[so * 4 + 0];
        const float c1 = sM[so * 4 + 1];
        const float c2 = sM[so * 4 + 2];
        const float c3 = sM[so * 4 + 3];
        float4 r;
        r.x = a * v0.x + c1 * v1.x + c2 * v2.x + c3 * v3.x;
        r.y = a * v0.y + c1 * v1.y + c2 * v2.y + c3 * v3.y;
        r.z = a * v0.z + c1 * v1.z + c2 * v2.z + c3 * v3.z;
        r.w = a * v0.w + c1 * v1.w + c2 * v2.w + c3 * v3.w;
        ob[(size_t)so * PLANE_F4] = r;
    }
}

extern "C" void kernel_launch(void* const* d_in, const int* in_sizes, int n_in,
                              void* d_out, int out_size) {
    const float* residuals  = (const float*)d_in[0];   // [8, 4096, 2048]
    const float* res_logits = (const float*)d_in[1];   // [4, 4]
    const float* pre_logits = (const float*)d_in[2];   // [4]
    const float* post_logits= (const float*)d_in[3];   // [4]
    float* out = (float*)d_out;

    hc_setup_kernel<<<1, 32>>>(res_logits, pre_logits, post_logits);

    const unsigned total_threads = NB * PLANE_F4;      // 4,194,304
    const unsigned blocks = total_threads / 256u;      // 16384
    hc_mix_kernel<<<blocks, 256>>>((const float4*)residuals, (float4*)out);
}

// round 11
// speedup vs baseline: 1.0566x; 1.0566x over previous
#include <cuda_runtime.h>
#include <math.h>

// HyperConnections on GB300.
// Algebraic collapse: out[(b,so),t,d] = sum_s M[so][s] * in[(b,s),t,d]
//   M[so][s] = H_res[so][s] + H_post[so] * H_pre[s]
// H_res = Sinkhorn(H_res_logits, 10 iters, tau=0.05), H_pre/H_post = softmax.
//
// Shapes: residuals [B*S, T, D] = [8, 4096, 2048] fp32. Plane = T*D = 2^23 floats
//         = 2^21 float4. B=2, S=4.

#define NSTREAMS 4
#define PLANE_F4 (4096 * 2048 / 4)   // 2097152 = 1 << 21
#define PLANE_SHIFT 21
#define NB 2

__device__ float g_M[16];

// ---------------------------------------------------------------------------
// Setup: Sinkhorn (log-domain, 10 iters) + softmaxes -> combined 4x4 mix M.
// Single thread, on fast MUFU intrinsics (__expf/__logf = 2 SASS instr each)
// instead of libm software sequences. Serial chain ~20x shorter.
// ---------------------------------------------------------------------------
__global__ void hc_setup_kernel(const float* __restrict__ res_logits,
                                const float* __restrict__ pre_logits,
                                const float* __restrict__ post_logits) {
    if (threadIdx.x != 0 || blockIdx.x != 0) return;

    const float tau = 0.05f;
    float Z[NSTREAMS][NSTREAMS];
    #pragma unroll
    for (int i = 0; i < NSTREAMS; i++)
        #pragma unroll
        for (int j = 0; j < NSTREAMS; j++)
            Z[i][j] = res_logits[i * NSTREAMS + j] / tau;

    float u[NSTREAMS], v[NSTREAMS];
    #pragma unroll
    for (int i = 0; i < NSTREAMS; i++) { u[i] = 0.0f; v[i] = 0.0f; }

    const float log_marginal = -__logf((float)NSTREAMS);

    for (int it = 0; it < 10; it++) {
        // u = log_marginal - logsumexp_j(Z[i][j] + v[j])
        #pragma unroll
        for (int i = 0; i < NSTREAMS; i++) {
            float m = -INFINITY;
            #pragma unroll
            for (int j = 0; j < NSTREAMS; j++) m = fmaxf(m, Z[i][j] + v[j]);
            float s = 0.0f;
            #pragma unroll
            for (int j = 0; j < NSTREAMS; j++) s += __expf(Z[i][j] + v[j] - m);
            u[i] = log_marginal - (m + __logf(s));
        }
        // v = log_marginal - logsumexp_i(Z[i][j] + u[i])   (uses updated u)
        #pragma unroll
        for (int j = 0; j < NSTREAMS; j++) {
            float m = -INFINITY;
            #pragma unroll
            for (int i = 0; i < NSTREAMS; i++) m = fmaxf(m, Z[i][j] + u[i]);
            float s = 0.0f;
            #pragma unroll
            for (int i = 0; i < NSTREAMS; i++) s += __expf(Z[i][j] + u[i] - m);
            v[j] = log_marginal - (m + __logf(s));
        }
    }

    // softmax(H_pre_logits), softmax(H_post_logits)
    float Hpre[NSTREAMS], Hpost[NSTREAMS];
    {
        float m = -INFINITY;
        #pragma unroll
        for (int i = 0; i < NSTREAMS; i++) m = fmaxf(m, pre_logits[i]);
        float s = 0.0f;
        #pragma unroll
        for (int i = 0; i < NSTREAMS; i++) { Hpre[i] = __expf(pre_logits[i] - m); s += Hpre[i]; }
        #pragma unroll
        for (int i = 0; i < NSTREAMS; i++) Hpre[i] /= s;
    }
    {
        float m = -INFINITY;
        #pragma unroll
        for (int i = 0; i < NSTREAMS; i++) m = fmaxf(m, post_logits[i]);
        float s = 0.0f;
        #pragma unroll
        for (int i = 0; i < NSTREAMS; i++) { Hpost[i] = __expf(post_logits[i] - m); s += Hpost[i]; }
        #pragma unroll
        for (int i = 0; i < NSTREAMS; i++) Hpost[i] /= s;
    }

    // M[so][s] = H_res[so][s] + H_post[so]*H_pre[s],  H_res = exp(Z+u+v)*n
    #pragma unroll
    for (int so = 0; so < NSTREAMS; so++)
        #pragma unroll
        for (int s = 0; s < NSTREAMS; s++)
            g_M[so * NSTREAMS + s] =
                __expf(Z[so][s] + u[so] + v[s]) * (float)NSTREAMS + Hpost[so] * Hpre[s];
}

// ---------------------------------------------------------------------------
// Streaming 4x4 stream mix. Two consecutive float4 per thread per stream plane
// (MLP_p1 = 8 front-batched loads). Streaming cache hints: every element is
// touched exactly once, so evict-first on both loads and stores.
// Traffic: 256 MB read + 256 MB write.
// ---------------------------------------------------------------------------
__global__ __launch_bounds__(256)
void hc_mix_kernel(const float4* __restrict__ x, float4* __restrict__ out) {
    __shared__ float sM[16];
    if (threadIdx.x < 16) sM[threadIdx.x] = g_M[threadIdx.x];
    __syncthreads();

    unsigned tid = blockIdx.x * 256u + threadIdx.x;       // over (B*PLANE_F4)/2
    unsigned idx = tid * 2u;                              // float4 index
    unsigned b   = idx >> PLANE_SHIFT;                    // 0..1
    unsigned i   = idx & (PLANE_F4 - 1u);

    const float4* base = x   + (size_t)b * (NSTREAMS * (size_t)PLANE_F4) + i;
    float4*       ob   = out + (size_t)b * (NSTREAMS * (size_t)PLANE_F4) + i;

    // Front-batch all 8 loads for maximum MLP.
    float4 v00 = __ldcs(base + 0 * (size_t)PLANE_F4);
    float4 v01 = __ldcs(base + 0 * (size_t)PLANE_F4 + 1);
    float4 v10 = __ldcs(base + 1 * (size_t)PLANE_F4);
    float4 v11 = __ldcs(base + 1 * (size_t)PLANE_F4 + 1);
    float4 v20 = __ldcs(base + 2 * (size_t)PLANE_F4);
    float4 v21 = __ldcs(base + 2 * (size_t)PLANE_F4 + 1);
    float4 v30 = __ldcs(base + 3 * (size_t)PLANE_F4);
    float4 v31 = __ldcs(base + 3 * (size_t)PLANE_F4 + 1);

    #pragma unroll
    for (int so = 0; so < NSTREAMS; so++) {
        const float c0 = sM[so * 4 + 0];
        const float c1 = sM[so * 4 + 1];
        const float c2 = sM[so * 4 + 2];
        const float c3 = sM[so * 4 + 3];
        float4 r0, r1;
        r0.x = c0 * v00.x + c1 * v10.x + c2 * v20.x + c3 * v30.x;
        r0.y = c0 * v00.y + c1 * v10.y + c2 * v20.y + c3 * v30.y;
        r0.z = c0 * v00.z + c1 * v10.z + c2 * v20.z + c3 * v30.z;
        r0.w = c0 * v00.w + c1 * v10.w + c2 * v20.w + c3 * v30.w;
        r1.x = c0 * v01.x + c1 * v11.x + c2 * v21.x + c3 * v31.x;
        r1.y = c0 * v01.y + c1 * v11.y + c2 * v21.y + c3 * v31.y;
        r1.z = c0 * v01.z + c1 * v11.z + c2 * v21.z + c3 * v31.z;
        r1.w = c0 * v01.w + c1 * v11.w + c2 * v21.w + c3 * v31.w;
        __stcs(ob + (size_t)so * PLANE_F4,     r0);
        __stcs(ob + (size_t)so * PLANE_F4 + 1, r1);
    }
}

extern "C" void kernel_launch(void* const* d_in, const int* in_sizes, int n_in,
                              void* d_out, int out_size) {
    const float* residuals   = (const float*)d_in[0];   // [8, 4096, 2048]
    const float* res_logits  = (const float*)d_in[1];   // [4, 4]
    const float* pre_logits  = (const float*)d_in[2];   // [4]
    const float* post_logits = (const float*)d_in[3];   // [4]
    float* out = (float*)d_out;

    hc_setup_kernel<<<1, 32>>>(res_logits, pre_logits, post_logits);

    const unsigned total_threads = (NB * PLANE_F4) / 2;  // 2,097,152
    const unsigned blocks = total_threads / 256u;        // 8192
    hc_mix_kernel<<<blocks, 256>>>((const float4*)residuals, (float4*)out);
}